// round 7
// baseline (speedup 1.0000x reference)
#include <cuda_runtime.h>
#include <cuda_bf16.h>

#define NA 51   // n_atom

// Scratch for deterministic single-kernel loss reduction (no cudaMalloc allowed).
__device__ float        g_partials[8192];
__device__ unsigned int g_count = 0;

__global__ __launch_bounds__(128, 16) void dtd_kernel(
    const float* __restrict__ dist,          // (B, N, NA)
    const float* __restrict__ next_n_dist,   // (B, N, NA)
    const int*   __restrict__ action,        // (B,)
    const int*   __restrict__ next_n_action, // (B,)
    const float* __restrict__ reward,        // (T, B)
    const unsigned int* __restrict__ done,   // (B,) 32-bit bool encoding
    const float* __restrict__ weight,        // (B,)
    const float* __restrict__ gamma_p,
    const float* __restrict__ vmin_p,
    const float* __restrict__ vmax_p,
    float* __restrict__ out,                 // flattened (loss?, td_err[B])
    int B, int N, int T, int has_loss, int td_off)
{
    __shared__ float s_log[4][4][64];        // per-warp, per-element log p rows
    __shared__ float s_w[4];
    __shared__ int   s_last;

    const int warp = threadIdx.x >> 5;
    const int lane = threadIdx.x & 31;
    const int b0   = blockIdx.x * 16 + warp * 4;   // 4 batch elements per warp
    const unsigned FULL = 0xffffffffu;

    const float gamma  = __ldg(gamma_p);
    const float v_min  = __ldg(vmin_p);
    const float v_max  = __ldg(vmax_p);
    const float inv_dz = (float)(NA - 1) / (v_max - v_min);
    const float fMax   = (float)(NA - 1);

    float* __restrict__ td_out = out + td_off;

    // ---- scalar per-element loads (broadcast, warp-uniform per i) ----
    int  bc[4], a[4], na[4];
    bool dn[4];
    #pragma unroll
    for (int i = 0; i < 4; i++) {
        bc[i] = min(b0 + i, B - 1);
        a[i]  = __ldg(&action[bc[i]]);
        na[i] = __ldg(&next_n_action[bc[i]]);
        dn[i] = (__ldg(&done[bc[i]]) != 0u);
    }
    float wlane = 0.0f;
    if (lane < 4) wlane = __ldg(&weight[min(b0 + lane, B - 1)]);

    // ---- n-step return: lanes 0..3 each own one element, then broadcast ----
    float rv = 0.0f;
    {
        const int bl = min(b0 + (lane & 3), B - 1);
        if (lane < 4) {
            float gf = 1.0f;
            for (int t = 0; t < T; t++) {
                rv = fmaf(gf, __ldg(&reward[t * B + bl]), rv);
                gf *= gamma;
            }
        }
    }
    float gT = 1.0f;
    for (int t = 0; t < T; t++) gT *= gamma;

    float r[4];
    #pragma unroll
    for (int i = 0; i < 4; i++) r[i] = __shfl_sync(FULL, rv, i);

    // ---- front-batched row gathers ----
    float plo[4], phi[4], tlo[4], thi[4];
    #pragma unroll
    for (int i = 0; i < 4; i++) {
        const unsigned op = (unsigned)(bc[i] * N + a[i]) * NA;
        plo[i] = __ldg(&dist[op + lane]);
        phi[i] = (lane < NA - 32) ? __ldg(&dist[op + lane + 32]) : 1.0f;
    }
    #pragma unroll
    for (int i = 0; i < 4; i++) {
        tlo[i] = 0.0f; thi[i] = 0.0f;
        if (!dn[i]) {                          // warp-uniform branch
            const unsigned ot = (unsigned)(bc[i] * N + na[i]) * NA;
            tlo[i] = __ldg(&next_n_dist[ot + lane]);
            if (lane < NA - 32) thi[i] = __ldg(&next_n_dist[ot + lane + 32]);
        }
    }

    // ---- logs into per-warp shared (hi half unconditional: log(1)=0 pad) ----
    #pragma unroll
    for (int i = 0; i < 4; i++) {
        s_log[warp][i][lane]      = __logf(plo[i]);
        s_log[warp][i][lane + 32] = __logf(phi[i]);
    }
    __syncwarp();

    const float jf0 = (float)lane;
    const float jf1 = (float)(lane + 32);

    float acc[4], dval[4];
    #pragma unroll
    for (int i = 0; i < 4; i++) {
        const float* sl = s_log[warp][i];
        acc[i] = 0.0f; dval[i] = 0.0f;
        if (dn[i]) {
            // target_z identical across atoms; sum(td)=1 -> one interpolation
            float bb = fminf(fmaxf((r[i] - v_min) * inv_dz, 0.0f), fMax);
            int   l  = max(__float2int_ru(bb) - 1, 0);
            float fl = (float)l;
            float lo = sl[l], hi = sl[l + 1];
            dval[i] = -fmaf(bb - fl, hi - lo, lo);
        } else {
            // linearized: bb_j = clamp(c + gT*j, 0, NA-1)
            const float c = (fmaf(gT, v_min, r[i]) - v_min) * inv_dz;
            {   // atoms j = lane
                float bb = fminf(fmaxf(fmaf(gT, jf0, c), 0.0f), fMax);
                int   l  = max(__float2int_ru(bb) - 1, 0);
                float fl = (float)l;
                float lo = sl[l], hi = sl[l + 1];
                acc[i] = tlo[i] * fmaf(bb - fl, hi - lo, lo);
            }
            {   // atoms j = lane+32 (thi=0 for lanes >= 19)
                float bb = fminf(fmaxf(fmaf(gT, jf1, c), 0.0f), fMax);
                int   l  = max(__float2int_ru(bb) - 1, 0);
                float fl = (float)l;
                float lo = sl[l], hi = sl[l + 1];
                acc[i] = fmaf(thi[i], fmaf(bb - fl, hi - lo, lo), acc[i]);
            }
        }
    }

    // ---- fused 4-element reduction: element i's total lands in lanes lane&3==i ----
    #pragma unroll
    for (int i = 0; i < 4; i++) {
        acc[i] += __shfl_xor_sync(FULL, acc[i], 1);
        acc[i] += __shfl_xor_sync(FULL, acc[i], 2);
    }
    const int e = lane & 3;
    float v = acc[0];
    if (e == 1) v = acc[1];
    if (e == 2) v = acc[2];
    if (e == 3) v = acc[3];
    v += __shfl_xor_sync(FULL, v, 4);
    v += __shfl_xor_sync(FULL, v, 8);
    v += __shfl_xor_sync(FULL, v, 16);
    float tv = -v;
    if (e == 0 && dn[0]) tv = dval[0];
    if (e == 1 && dn[1]) tv = dval[1];
    if (e == 2 && dn[2]) tv = dval[2];
    if (e == 3 && dn[3]) tv = dval[3];

    // ---- coalesced td_err store + weighted partial (lanes 0-3) ----
    float ws = 0.0f;
    if (lane < 4 && b0 + lane < B) {
        td_out[b0 + lane] = tv;
        ws = tv * wlane;
    }
    ws += __shfl_xor_sync(FULL, ws, 1);
    ws += __shfl_xor_sync(FULL, ws, 2);
    if (lane == 0) s_w[warp] = ws;
    __syncthreads();

    // ---- block partial + last-block deterministic loss reduction ----
    if (threadIdx.x == 0) {
        float pv = s_w[0] + s_w[1] + s_w[2] + s_w[3];
        g_partials[blockIdx.x] = pv;
        __threadfence();
        unsigned int ticket = atomicAdd(&g_count, 1u);
        s_last = (ticket == gridDim.x - 1) ? 1 : 0;
    }
    __syncthreads();

    if (s_last) {
        __threadfence();
        float pv = 0.0f;
        const volatile float* gp = g_partials;
        for (int i = threadIdx.x; i < (int)gridDim.x; i += blockDim.x)
            pv += gp[i];
        #pragma unroll
        for (int o = 16; o; o >>= 1)
            pv += __shfl_xor_sync(FULL, pv, o);
        if (lane == 0) s_w[warp] = pv;
        __syncthreads();
        if (threadIdx.x < 32) {
            pv = (lane < 4) ? s_w[lane] : 0.0f;
            pv += __shfl_xor_sync(FULL, pv, 1);
            pv += __shfl_xor_sync(FULL, pv, 2);
            if (threadIdx.x == 0) {
                if (has_loss) out[0] = pv * (1.0f / (float)B);
                g_count = 0;                    // reset for next graph replay
            }
        }
    }
}

extern "C" void kernel_launch(void* const* d_in, const int* in_sizes, int n_in,
                              void* d_out, int out_size)
{
    const float*        dist          = (const float*)d_in[0];
    const float*        next_n_dist   = (const float*)d_in[1];
    const int*          action        = (const int*)d_in[2];
    const int*          next_n_action = (const int*)d_in[3];
    const float*        reward        = (const float*)d_in[4];
    const unsigned int* done          = (const unsigned int*)d_in[5];
    const float*        weight        = (const float*)d_in[6];
    const float*        gamma_p       = (const float*)d_in[7];
    const float*        vmin_p        = (const float*)d_in[8];
    const float*        vmax_p        = (const float*)d_in[9];

    const int B = in_sizes[2];                 // action is (B,)
    const int N = in_sizes[0] / (B * NA);      // dist is (B, N, NA)
    const int T = in_sizes[4] / B;             // reward is (T, B)

    float* out = (float*)d_out;
    const int td_off   = out_size - B;         // td_err is the trailing B elements
    const int has_loss = (out_size > B) ? 1 : 0;

    const int blocks = (B + 15) / 16;          // 16 batch elements per 128-thread block
    dtd_kernel<<<blocks, 128>>>(dist, next_n_dist, action, next_n_action,
                                reward, done, weight, gamma_p, vmin_p, vmax_p,
                                out, B, N, T, has_loss, td_off);
}

// round 8
// speedup vs baseline: 1.5000x; 1.5000x over previous
#include <cuda_runtime.h>
#include <cuda_bf16.h>

#define NA 51   // n_atom

// Scratch for deterministic single-kernel loss reduction (no cudaMalloc allowed).
__device__ float        g_partials[8192];
__device__ unsigned int g_count = 0;

__global__ __launch_bounds__(512) void dtd_kernel(
    const float* __restrict__ dist,          // (B, N, NA)
    const float* __restrict__ next_n_dist,   // (B, N, NA)
    const int*   __restrict__ action,        // (B,)
    const int*   __restrict__ next_n_action, // (B,)
    const float* __restrict__ reward,        // (T, B)
    const unsigned int* __restrict__ done,   // (B,) 32-bit bool encoding
    const float* __restrict__ weight,        // (B,)
    const float* __restrict__ gamma_p,
    const float* __restrict__ vmin_p,
    const float* __restrict__ vmax_p,
    float* __restrict__ out,                 // flattened (loss?, td_err[B])
    int B, int N, int T, int has_loss, int td_off)
{
    __shared__ float s_log[16][4][64];       // per-warp, per-element log p rows
    __shared__ float s_w[16];
    __shared__ int   s_last;

    const int warp = threadIdx.x >> 5;
    const int lane = threadIdx.x & 31;
    const int b0   = blockIdx.x * 64 + warp * 4;   // 4 batch elements per warp
    const unsigned FULL = 0xffffffffu;

    const float gamma  = __ldg(gamma_p);
    const float v_min  = __ldg(vmin_p);
    const float v_max  = __ldg(vmax_p);
    const float inv_dz = (float)(NA - 1) / (v_max - v_min);
    const float fMax   = (float)(NA - 1);

    float* __restrict__ td_out = out + td_off;

    // ---- scalar per-element loads (broadcast, warp-uniform per i) ----
    int  bc[4], a[4], na[4];
    bool dn[4];
    #pragma unroll
    for (int i = 0; i < 4; i++) {
        bc[i] = min(b0 + i, B - 1);
        a[i]  = __ldg(&action[bc[i]]);
        na[i] = __ldg(&next_n_action[bc[i]]);
        dn[i] = (__ldg(&done[bc[i]]) != 0u);
    }
    float wlane = 0.0f;
    if (lane < 4) wlane = __ldg(&weight[min(b0 + lane, B - 1)]);

    // ---- n-step return: lanes 0..3 each own one element, then broadcast ----
    float rv = 0.0f;
    {
        const int bl = min(b0 + (lane & 3), B - 1);
        if (lane < 4) {
            float gf = 1.0f;
            for (int t = 0; t < T; t++) {
                rv = fmaf(gf, __ldg(&reward[t * B + bl]), rv);
                gf *= gamma;
            }
        }
    }
    float gT = 1.0f;
    for (int t = 0; t < T; t++) gT *= gamma;

    float r[4];
    #pragma unroll
    for (int i = 0; i < 4; i++) r[i] = __shfl_sync(FULL, rv, i);

    // ---- front-batched row gathers ----
    float plo[4], phi[4], tlo[4], thi[4];
    #pragma unroll
    for (int i = 0; i < 4; i++) {
        const unsigned op = (unsigned)(bc[i] * N + a[i]) * NA;
        plo[i] = __ldg(&dist[op + lane]);
        phi[i] = (lane < NA - 32) ? __ldg(&dist[op + lane + 32]) : 1.0f;
    }
    #pragma unroll
    for (int i = 0; i < 4; i++) {
        tlo[i] = 0.0f; thi[i] = 0.0f;
        if (!dn[i]) {                          // warp-uniform branch
            const unsigned ot = (unsigned)(bc[i] * N + na[i]) * NA;
            tlo[i] = __ldg(&next_n_dist[ot + lane]);
            if (lane < NA - 32) thi[i] = __ldg(&next_n_dist[ot + lane + 32]);
        }
    }

    // ---- logs into per-warp shared (hi half unconditional: log(1)=0 pad) ----
    #pragma unroll
    for (int i = 0; i < 4; i++) {
        s_log[warp][i][lane]      = __logf(plo[i]);
        s_log[warp][i][lane + 32] = __logf(phi[i]);
    }
    __syncwarp();

    const float jf0 = (float)lane;
    const float jf1 = (float)(lane + 32);

    float acc[4], dval[4];
    #pragma unroll
    for (int i = 0; i < 4; i++) {
        const float* sl = s_log[warp][i];
        acc[i] = 0.0f; dval[i] = 0.0f;
        if (dn[i]) {
            // target_z identical across atoms; sum(td)=1 -> one interpolation
            float bb = fminf(fmaxf((r[i] - v_min) * inv_dz, 0.0f), fMax);
            int   l  = max(__float2int_ru(bb) - 1, 0);
            float fl = (float)l;
            float lo = sl[l], hi = sl[l + 1];
            dval[i] = -fmaf(bb - fl, hi - lo, lo);
        } else {
            // linearized: bb_j = clamp(c + gT*j, 0, NA-1)
            const float c = (fmaf(gT, v_min, r[i]) - v_min) * inv_dz;
            {   // atoms j = lane
                float bb = fminf(fmaxf(fmaf(gT, jf0, c), 0.0f), fMax);
                int   l  = max(__float2int_ru(bb) - 1, 0);
                float fl = (float)l;
                float lo = sl[l], hi = sl[l + 1];
                acc[i] = tlo[i] * fmaf(bb - fl, hi - lo, lo);
            }
            {   // atoms j = lane+32 (thi=0 for lanes >= 19)
                float bb = fminf(fmaxf(fmaf(gT, jf1, c), 0.0f), fMax);
                int   l  = max(__float2int_ru(bb) - 1, 0);
                float fl = (float)l;
                float lo = sl[l], hi = sl[l + 1];
                acc[i] = fmaf(thi[i], fmaf(bb - fl, hi - lo, lo), acc[i]);
            }
        }
    }

    // ---- fused 4-element reduction: element i's total lands in lanes lane&3==i ----
    #pragma unroll
    for (int i = 0; i < 4; i++) {
        acc[i] += __shfl_xor_sync(FULL, acc[i], 1);
        acc[i] += __shfl_xor_sync(FULL, acc[i], 2);
    }
    const int e = lane & 3;
    float v = acc[0];
    if (e == 1) v = acc[1];
    if (e == 2) v = acc[2];
    if (e == 3) v = acc[3];
    v += __shfl_xor_sync(FULL, v, 4);
    v += __shfl_xor_sync(FULL, v, 8);
    v += __shfl_xor_sync(FULL, v, 16);
    float tv = -v;
    if (e == 0 && dn[0]) tv = dval[0];
    if (e == 1 && dn[1]) tv = dval[1];
    if (e == 2 && dn[2]) tv = dval[2];
    if (e == 3 && dn[3]) tv = dval[3];

    // ---- coalesced td_err store + weighted partial (lanes 0-3) ----
    float ws = 0.0f;
    if (lane < 4 && b0 + lane < B) {
        td_out[b0 + lane] = tv;
        ws = tv * wlane;
    }
    ws += __shfl_xor_sync(FULL, ws, 1);
    ws += __shfl_xor_sync(FULL, ws, 2);
    if (lane == 0) s_w[warp] = ws;
    __syncthreads();

    // ---- block partial + last-block deterministic loss reduction ----
    if (threadIdx.x == 0) {
        float pv = 0.0f;
        #pragma unroll
        for (int w = 0; w < 16; w++) pv += s_w[w];
        g_partials[blockIdx.x] = pv;
        __threadfence();
        unsigned int ticket = atomicAdd(&g_count, 1u);
        s_last = (ticket == gridDim.x - 1) ? 1 : 0;
    }
    __syncthreads();

    if (s_last) {
        __threadfence();
        // Unordered L2 loads (visible after fence+ticket acquire): all loads
        // issue back-to-back -> ~1 DRAM/L2 round trip instead of a serialized
        // volatile chain.
        float pv = 0.0f;
        for (int i = threadIdx.x; i < (int)gridDim.x; i += blockDim.x)
            pv += __ldcg(&g_partials[i]);
        #pragma unroll
        for (int o = 16; o; o >>= 1)
            pv += __shfl_xor_sync(FULL, pv, o);
        if (lane == 0) s_w[warp] = pv;
        __syncthreads();
        if (threadIdx.x < 32) {
            pv = (lane < 16) ? s_w[lane] : 0.0f;
            #pragma unroll
            for (int o = 8; o; o >>= 1)
                pv += __shfl_xor_sync(FULL, pv, o);
            if (threadIdx.x == 0) {
                if (has_loss) out[0] = pv * (1.0f / (float)B);
                g_count = 0;                    // reset for next graph replay
            }
        }
    }
}

extern "C" void kernel_launch(void* const* d_in, const int* in_sizes, int n_in,
                              void* d_out, int out_size)
{
    const float*        dist          = (const float*)d_in[0];
    const float*        next_n_dist   = (const float*)d_in[1];
    const int*          action        = (const int*)d_in[2];
    const int*          next_n_action = (const int*)d_in[3];
    const float*        reward        = (const float*)d_in[4];
    const unsigned int* done          = (const unsigned int*)d_in[5];
    const float*        weight        = (const float*)d_in[6];
    const float*        gamma_p       = (const float*)d_in[7];
    const float*        vmin_p        = (const float*)d_in[8];
    const float*        vmax_p        = (const float*)d_in[9];

    const int B = in_sizes[2];                 // action is (B,)
    const int N = in_sizes[0] / (B * NA);      // dist is (B, N, NA)
    const int T = in_sizes[4] / B;             // reward is (T, B)

    float* out = (float*)d_out;
    const int td_off   = out_size - B;         // td_err is the trailing B elements
    const int has_loss = (out_size > B) ? 1 : 0;

    const int blocks = (B + 63) / 64;          // 64 batch elements per 512-thread block
    dtd_kernel<<<blocks, 512>>>(dist, next_n_dist, action, next_n_action,
                                reward, done, weight, gamma_p, vmin_p, vmax_p,
                                out, B, N, T, has_loss, td_off);
}